// round 2
// baseline (speedup 1.0000x reference)
#include <cuda_runtime.h>
#include <math.h>

// Problem constants
#define BATCH 128
#define TLEN 160000

// Decomposition
#define CHUNK 125                 // samples per thread (odd -> conflict-free smem stride)
#define NTHREADS 128              // threads per block
#define REGION (CHUNK * NTHREADS) // 16000 samples per block
#define WARM 32                   // warmup samples (pole decay 0.414^32 ~ 6e-13)
#define SMEM_FLOATS (REGION + WARM)   // 16032 floats = 64128 bytes
#define BLOCKS_PER_CH (TLEN / REGION) // 10
#define NBLOCKS (BATCH * BLOCKS_PER_CH)

__global__ void __launch_bounds__(NTHREADS)
biquad_kernel(const float* __restrict__ x, float* __restrict__ y,
              float b0, float b1, float b2, float a1, float a2)
{
    extern __shared__ float s[];  // [WARM halo | REGION samples]
    const int tid = threadIdx.x;
    const int blk = blockIdx.x;
    const int ch  = blk / BLOCKS_PER_CH;
    const int s0  = (blk % BLOCKS_PER_CH) * REGION;
    const long base = (long)ch * TLEN + s0;

    // ---- Stage input: coalesced float4 loads of the 16000-sample region ----
    {
        const float4* __restrict__ xin = (const float4*)(x + base);
        float4* s4 = (float4*)(s + WARM);   // WARM=32 floats = 128B, 16B-aligned
        #pragma unroll 4
        for (int i = tid; i < REGION / 4; i += NTHREADS)
            s4[i] = xin[i];
        // 32-sample halo before the region (zeros at channel start == exact zero ICs)
        if (tid < WARM)
            s[tid] = (s0 == 0) ? 0.0f : x[base - WARM + tid];
    }
    __syncthreads();

    // ---- Warmup: 32 steps from zero state, read-only (smem stride 125 -> no conflicts) ----
    const int p = WARM + tid * CHUNK;
    float x1 = 0.0f, x2 = 0.0f, y1 = 0.0f, y2 = 0.0f;
    #pragma unroll 8
    for (int t = 0; t < WARM; ++t) {
        float xv = s[p - WARM + t];
        float yv = b0 * xv + b1 * x1 + b2 * x2 - a1 * y1 - a2 * y2;
        x2 = x1; x1 = xv;
        y2 = y1; y1 = yv;
    }
    __syncthreads();  // warmups (which read into neighbors' chunks) done before in-place writes

    // ---- Main: filter chunk in place in SMEM ----
    #pragma unroll 5
    for (int t = 0; t < CHUNK; ++t) {
        float xv = s[p + t];
        float yv = b0 * xv + b1 * x1 + b2 * x2 - a1 * y1 - a2 * y2;
        x2 = x1; x1 = xv;
        y2 = y1; y1 = yv;
        s[p + t] = yv;
    }
    __syncthreads();

    // ---- Store output: coalesced float4 stores ----
    {
        const float4* s4 = (const float4*)(s + WARM);
        float4* __restrict__ yout = (float4*)(y + base);
        #pragma unroll 4
        for (int i = tid; i < REGION / 4; i += NTHREADS)
            yout[i] = s4[i];
    }
}

extern "C" void kernel_launch(void* const* d_in, const int* in_sizes, int n_in,
                              void* d_out, int out_size)
{
    const float* x = (const float*)d_in[0];
    float* y = (float*)d_out;

    // torchaudio lowpass_biquad coefficients (double math, then float32 — matches reference)
    const double PI = 3.14159265358979323846;
    double w0    = 2.0 * PI * 8000.0 / 32000.0;
    double alpha = sin(w0) / (2.0 * 0.707);
    double cw    = cos(w0);
    double b0d = (1.0 - cw) / 2.0;
    double b1d = 1.0 - cw;
    double b2d = b0d;
    double a0d = 1.0 + alpha;
    double a1d = -2.0 * cw;
    double a2d = 1.0 - alpha;
    float b0 = (float)(b0d / a0d);
    float b1 = (float)(b1d / a0d);
    float b2 = (float)(b2d / a0d);
    float a1 = (float)(a1d / a0d);
    float a2 = (float)(a2d / a0d);

    // 64128 B dynamic smem > 48KB default: raise the cap (non-stream API, capture-safe)
    cudaFuncSetAttribute(biquad_kernel,
                         cudaFuncAttributeMaxDynamicSharedMemorySize,
                         SMEM_FLOATS * (int)sizeof(float));

    biquad_kernel<<<NBLOCKS, NTHREADS, SMEM_FLOATS * sizeof(float)>>>(
        x, y, b0, b1, b2, a1, a2);
}

// round 3
// speedup vs baseline: 1.4596x; 1.4596x over previous
#include <cuda_runtime.h>
#include <math.h>

// Problem constants
#define BATCH 128
#define TLEN 160000

// Decomposition (small regions -> high occupancy -> deep memory pipeline)
#define CHUNK 25                  // samples per thread (odd -> conflict-free smem stride)
#define NTHREADS 128              // threads per block
#define REGION (CHUNK * NTHREADS) // 3200 samples per block
#define WARM 32                   // warmup samples (pole decay 0.414^32 ~ 6e-13)
#define SMEM_FLOATS (REGION + WARM)   // 3232 floats = 12928 bytes
#define BLOCKS_PER_CH (TLEN / REGION) // 50
#define NBLOCKS (BATCH * BLOCKS_PER_CH) // 6400

__global__ void __launch_bounds__(NTHREADS)
biquad_kernel(const float* __restrict__ x, float* __restrict__ y,
              float b0, float b1, float b2, float a1, float a2)
{
    extern __shared__ float s[];  // [WARM halo | REGION samples]
    const int tid = threadIdx.x;
    const int blk = blockIdx.x;
    const int ch  = blk / BLOCKS_PER_CH;
    const int s0  = (blk % BLOCKS_PER_CH) * REGION;
    const long base = (long)ch * TLEN + s0;

    // ---- Stage input: coalesced float4 loads of the 3200-sample region ----
    {
        const float4* __restrict__ xin = (const float4*)(x + base);
        float4* s4 = (float4*)(s + WARM);   // WARM=32 floats = 128B, 16B-aligned
        #pragma unroll
        for (int i = tid; i < REGION / 4; i += NTHREADS)   // 800/128 -> 7 iters (ragged)
            s4[i] = xin[i];
        // 32-sample halo before the region (zeros at channel start == exact zero ICs)
        if (tid < WARM)
            s[tid] = (s0 == 0) ? 0.0f : x[base - WARM + tid];
    }
    __syncthreads();

    // ---- Warmup: 32 steps from zero state, read-only (smem stride 25 -> no conflicts) ----
    const int p = WARM + tid * CHUNK;
    float x1 = 0.0f, x2 = 0.0f, y1 = 0.0f, y2 = 0.0f;
    #pragma unroll 8
    for (int t = 0; t < WARM; ++t) {
        float xv = s[p - WARM + t];
        float yv = b0 * xv + b1 * x1 + b2 * x2 - a1 * y1 - a2 * y2;
        x2 = x1; x1 = xv;
        y2 = y1; y1 = yv;
    }
    __syncthreads();  // warmup reads (into neighbors' chunks) done before in-place writes

    // ---- Main: filter chunk in place in SMEM ----
    #pragma unroll
    for (int t = 0; t < CHUNK; ++t) {
        float xv = s[p + t];
        float yv = b0 * xv + b1 * x1 + b2 * x2 - a1 * y1 - a2 * y2;
        x2 = x1; x1 = xv;
        y2 = y1; y1 = yv;
        s[p + t] = yv;
    }
    __syncthreads();

    // ---- Store output: coalesced float4 stores ----
    {
        const float4* s4 = (const float4*)(s + WARM);
        float4* __restrict__ yout = (float4*)(y + base);
        #pragma unroll
        for (int i = tid; i < REGION / 4; i += NTHREADS)
            yout[i] = s4[i];
    }
}

extern "C" void kernel_launch(void* const* d_in, const int* in_sizes, int n_in,
                              void* d_out, int out_size)
{
    const float* x = (const float*)d_in[0];
    float* y = (float*)d_out;

    // torchaudio lowpass_biquad coefficients (double math, then float32 — matches reference)
    const double PI = 3.14159265358979323846;
    double w0    = 2.0 * PI * 8000.0 / 32000.0;
    double alpha = sin(w0) / (2.0 * 0.707);
    double cw    = cos(w0);
    double b0d = (1.0 - cw) / 2.0;
    double b1d = 1.0 - cw;
    double b2d = b0d;
    double a0d = 1.0 + alpha;
    double a1d = -2.0 * cw;
    double a2d = 1.0 - alpha;
    float b0 = (float)(b0d / a0d);
    float b1 = (float)(b1d / a0d);
    float b2 = (float)(b2d / a0d);
    float a1 = (float)(a1d / a0d);
    float a2 = (float)(a2d / a0d);

    biquad_kernel<<<NBLOCKS, NTHREADS, SMEM_FLOATS * sizeof(float)>>>(
        x, y, b0, b1, b2, a1, a2);
}